// round 1
// baseline (speedup 1.0000x reference)
#include <cuda_runtime.h>
#include <math.h>

// ---------------------------------------------------------------------------
// GraphSAGE (3-layer, mean aggregator) on GB300, fp32.
//   layer: out = h @ W_self + (segsum(h[src]->dst) * inv_deg) @ W_neigh + b
//   relu after layers 0,1; log_softmax after layer 2.
// ---------------------------------------------------------------------------

#define N_NODES 100000
#define FEAT    128

// Scratch (allocation-free rule: __device__ globals).
__device__ __align__(256) float g_h1[(size_t)N_NODES * FEAT];
__device__ __align__(256) float g_h2[(size_t)N_NODES * FEAT];
__device__ __align__(256) float g_agg[(size_t)N_NODES * FEAT];
__device__ __align__(256) float g_deg[N_NODES];
__device__ __align__(256) float g_inv[N_NODES];

// ---------------------------------------------------------------------------
__global__ void zero_kernel(float4* __restrict__ p, int n4) {
    int i = blockIdx.x * blockDim.x + threadIdx.x;
    if (i < n4) p[i] = make_float4(0.f, 0.f, 0.f, 0.f);
}

__global__ void deg_kernel(const int* __restrict__ dst, int n_edges) {
    int i = blockIdx.x * blockDim.x + threadIdx.x;
    if (i < n_edges) atomicAdd(&g_deg[dst[i]], 1.0f);
}

__global__ void inv_kernel(int n) {
    int i = blockIdx.x * blockDim.x + threadIdx.x;
    if (i < n) g_inv[i] = 1.0f / fmaxf(g_deg[i], 1.0f);
}

// One warp per edge: lane l moves float4 l of the 128-float row (32*16B = 512B).
// Gather h[src] (L2-resident), reduce-add into g_agg[dst].
__global__ void scatter_kernel(const float4* __restrict__ h4,
                               const int* __restrict__ src,
                               const int* __restrict__ dst,
                               int n_edges) {
    int gtid = blockIdx.x * blockDim.x + threadIdx.x;
    int e    = gtid >> 5;
    int lane = gtid & 31;
    if (e >= n_edges) return;
    int s = __ldg(&src[e]);
    int d = __ldg(&dst[e]);
    float4 v = __ldg(&h4[(size_t)s * 32 + lane]);
    float4* p = reinterpret_cast<float4*>(g_agg) + (size_t)d * 32 + lane;
    asm volatile("red.global.add.v4.f32 [%0], {%1, %2, %3, %4};"
                 :: "l"(p), "f"(v.x), "f"(v.y), "f"(v.z), "f"(v.w)
                 : "memory");
}

// ---------------------------------------------------------------------------
// Fused SAGE-layer GEMM: out[n, BN] = [h | inv*agg] (n x 256) @ [Wself; Wneigh]
// (256 x BN) + bias, optional relu.
// 256 threads. BN=128 -> BM=64; BN=64 -> BM=128 (8192 outputs/block, 4x8/thread).
// SMEM: W concat (256*BN floats) + A tile transposed [k][row] padded.
// Both configs total exactly 200704 bytes.
// ---------------------------------------------------------------------------
#define SMEM_BYTES 200704

template<int BN, bool RELU>
__global__ void __launch_bounds__(256, 1)
sage_gemm(const float* h,
          const float* __restrict__ Wself,
          const float* __restrict__ Wneigh,
          const float* __restrict__ bias,
          float* out, int n, int n_tiles) {
    constexpr int BM      = 8192 / BN;   // 64 or 128
    constexpr int CG      = BN / 8;      // column groups
    constexpr int ASTRIDE = BM + 4;      // pad: 4-way store conflict, 16B-aligned v4 reads

    extern __shared__ float smem_buf[];
    float* Wsm = smem_buf;                 // [256][BN]
    float* Asm = smem_buf + 256 * BN;      // [256][ASTRIDE]

    const int tid = threadIdx.x;

    // Load concatenated weights (row-major, contiguous).
    for (int i = tid; i < 128 * BN; i += 256) Wsm[i] = Wself[i];
    for (int i = tid; i < 128 * BN; i += 256) Wsm[128 * BN + i] = Wneigh[i];

    const int cg = tid % CG;   // cols [cg*8, cg*8+8)
    const int rg = tid / CG;   // rows [rg*4, rg*4+4)

    float bv[8];
#pragma unroll
    for (int c = 0; c < 8; c++) bv[c] = bias[cg * 8 + c];

    // A-load role: thread tid owns concat-feature column k = tid for all BM rows.
    const int k = tid;
    const float* abase   = (k < 128) ? (h + k) : (g_agg + (k - 128));
    const bool   do_scale = (k >= 128);

    for (int tile = blockIdx.x; tile < n_tiles; tile += gridDim.x) {
        const int row0 = tile * BM;
        __syncthreads();   // Asm reuse guard (no-op first pass)

#pragma unroll 4
        for (int i = 0; i < BM; i++) {
            int r = row0 + i;
            float v = 0.0f;
            if (r < n) {
                v = __ldg(&abase[(size_t)r * 128]);
                if (do_scale) v *= g_inv[r];
            }
            Asm[k * ASTRIDE + i] = v;
        }
        __syncthreads();

        float acc[4][8];
#pragma unroll
        for (int r = 0; r < 4; r++)
#pragma unroll
            for (int c = 0; c < 8; c++) acc[r][c] = 0.0f;

#pragma unroll 4
        for (int kk = 0; kk < 256; kk++) {
            float4 a4 = *reinterpret_cast<const float4*>(&Asm[kk * ASTRIDE + rg * 4]);
            float4 w0 = *reinterpret_cast<const float4*>(&Wsm[kk * BN + cg * 8]);
            float4 w1 = *reinterpret_cast<const float4*>(&Wsm[kk * BN + cg * 8 + 4]);
            float av[4] = {a4.x, a4.y, a4.z, a4.w};
            float wv[8] = {w0.x, w0.y, w0.z, w0.w, w1.x, w1.y, w1.z, w1.w};
#pragma unroll
            for (int r = 0; r < 4; r++)
#pragma unroll
                for (int c = 0; c < 8; c++)
                    acc[r][c] = fmaf(av[r], wv[c], acc[r][c]);
        }

#pragma unroll
        for (int r = 0; r < 4; r++) {
            int grow = row0 + rg * 4 + r;
            if (grow < n) {
                float o[8];
#pragma unroll
                for (int c = 0; c < 8; c++) {
                    float v = acc[r][c] + bv[c];
                    if (RELU) v = fmaxf(v, 0.0f);
                    o[c] = v;
                }
                float4* po = reinterpret_cast<float4*>(&out[(size_t)grow * BN + cg * 8]);
                po[0] = make_float4(o[0], o[1], o[2], o[3]);
                po[1] = make_float4(o[4], o[5], o[6], o[7]);
            }
        }
    }
}

// ---------------------------------------------------------------------------
// In-place log_softmax over 64 classes. One warp per row, 2 cols/lane.
// ---------------------------------------------------------------------------
__global__ void logsoftmax_kernel(float* __restrict__ out, int n) {
    int gtid = blockIdx.x * blockDim.x + threadIdx.x;
    int row  = gtid >> 5;
    int lane = gtid & 31;
    if (row >= n) return;
    float* p = out + (size_t)row * 64;
    float a = p[lane];
    float b = p[lane + 32];
    float m = fmaxf(a, b);
#pragma unroll
    for (int o = 16; o > 0; o >>= 1)
        m = fmaxf(m, __shfl_xor_sync(0xFFFFFFFFu, m, o));
    float s = expf(a - m) + expf(b - m);
#pragma unroll
    for (int o = 16; o > 0; o >>= 1)
        s += __shfl_xor_sync(0xFFFFFFFFu, s, o);
    float l = m + logf(s);
    p[lane]      = a - l;
    p[lane + 32] = b - l;
}

// ---------------------------------------------------------------------------
extern "C" void kernel_launch(void* const* d_in, const int* in_sizes, int n_in,
                              void* d_out, int out_size) {
    const float* x   = (const float*)d_in[0];
    const int*   src = (const int*)  d_in[1];
    const int*   dst = (const int*)  d_in[2];
    const float* Ws0 = (const float*)d_in[3];
    const float* Wn0 = (const float*)d_in[4];
    const float* b0  = (const float*)d_in[5];
    const float* Ws1 = (const float*)d_in[6];
    const float* Wn1 = (const float*)d_in[7];
    const float* b1  = (const float*)d_in[8];
    const float* Ws2 = (const float*)d_in[9];
    const float* Wn2 = (const float*)d_in[10];
    const float* b2  = (const float*)d_in[11];
    float* out = (float*)d_out;

    const int n = N_NODES;
    const int E = in_sizes[1];

    float *h1p, *h2p, *aggp, *degp;
    cudaGetSymbolAddress((void**)&h1p,  g_h1);
    cudaGetSymbolAddress((void**)&h2p,  g_h2);
    cudaGetSymbolAddress((void**)&aggp, g_agg);
    cudaGetSymbolAddress((void**)&degp, g_deg);

    cudaFuncSetAttribute(sage_gemm<128, true>,
                         cudaFuncAttributeMaxDynamicSharedMemorySize, SMEM_BYTES);
    cudaFuncSetAttribute(sage_gemm<64, false>,
                         cudaFuncAttributeMaxDynamicSharedMemorySize, SMEM_BYTES);

    // Degrees (graph is fixed across layers).
    zero_kernel<<<(n / 4 + 255) / 256, 256>>>((float4*)degp, n / 4);
    deg_kernel<<<(E + 255) / 256, 256>>>(dst, E);
    inv_kernel<<<(n + 255) / 256, 256>>>(n);

    const int agg4 = n * FEAT / 4;
    const int zb   = (agg4 + 255) / 256;
    const int sb   = (E * 32 + 255) / 256;       // warp per edge
    const int t128 = (n + 63) / 64;              // BM=64 tiles
    const int t64  = (n + 127) / 128;            // BM=128 tiles

    // ---- layer 0: x -> h1 (relu) ----
    zero_kernel<<<zb, 256>>>((float4*)aggp, agg4);
    scatter_kernel<<<sb, 256>>>((const float4*)x, src, dst, E);
    sage_gemm<128, true><<<t128, 256, SMEM_BYTES>>>(x, Ws0, Wn0, b0, h1p, n, t128);

    // ---- layer 1: h1 -> h2 (relu) ----
    zero_kernel<<<zb, 256>>>((float4*)aggp, agg4);
    scatter_kernel<<<sb, 256>>>((const float4*)h1p, src, dst, E);
    sage_gemm<128, true><<<t128, 256, SMEM_BYTES>>>(h1p, Ws1, Wn1, b1, h2p, n, t128);

    // ---- layer 2: h2 -> out (64 classes), then log_softmax in place ----
    zero_kernel<<<zb, 256>>>((float4*)aggp, agg4);
    scatter_kernel<<<sb, 256>>>((const float4*)h2p, src, dst, E);
    sage_gemm<64, false><<<t64, 256, SMEM_BYTES>>>(h2p, Ws2, Wn2, b2, out, n, t64);

    logsoftmax_kernel<<<(n * 32 + 255) / 256, 256>>>(out, n);
}

// round 7
// speedup vs baseline: 1.5415x; 1.5415x over previous
#include <cuda_runtime.h>
#include <math.h>

// ---------------------------------------------------------------------------
// GraphSAGE (3-layer, mean aggregator) on GB300, fp32.
// Round 2 design (resubmit x5): CSR (counting sort by dst) + gather-only
// aggregation (no atomics), layer-2 project-before-aggregate,
// 2-block-occupancy K=128 GEMM.
// ---------------------------------------------------------------------------

#define N_NODES 100000
#define N_EDGES 1600000
#define FEAT    128

// Scratch (allocation-free rule: __device__ globals).
__device__ __align__(256) float g_h1[(size_t)N_NODES * FEAT];
__device__ __align__(256) float g_h2[(size_t)N_NODES * FEAT];
__device__ __align__(256) float g_agg[(size_t)N_NODES * FEAT];
__device__ __align__(256) float g_inv[N_NODES];
__device__ __align__(256) int   g_cnt[N_NODES + 1];
__device__ __align__(256) int   g_rowptr[N_NODES + 1];
__device__ __align__(256) int   g_cursor[N_NODES];
__device__ __align__(256) int   g_srcsort[N_EDGES];

// ---------------------------------------------------------------------------
__global__ void zero_int_kernel(int* __restrict__ p, int n) {
    int i = blockIdx.x * blockDim.x + threadIdx.x;
    if (i < n) p[i] = 0;
}

__global__ void count_kernel(const int* __restrict__ dst, int n_edges) {
    int i = blockIdx.x * blockDim.x + threadIdx.x;
    if (i < n_edges) atomicAdd(&g_cnt[dst[i]], 1);
}

// Single-block exclusive scan of g_cnt -> g_rowptr / g_cursor, plus inv_deg.
__global__ void scan_kernel() {
    __shared__ int sums[1024];
    const int t = threadIdx.x;
    const int chunk = (N_NODES + 1023) / 1024;   // 98
    const int beg = t * chunk;
    const int end = min(beg + chunk, N_NODES);
    int s = 0;
    for (int i = beg; i < end; i++) s += g_cnt[i];
    sums[t] = s;
    __syncthreads();
    for (int off = 1; off < 1024; off <<= 1) {
        int v = (t >= off) ? sums[t - off] : 0;
        __syncthreads();
        if (t >= off) sums[t] += v;
        __syncthreads();
    }
    int running = (t == 0) ? 0 : sums[t - 1];
    for (int i = beg; i < end; i++) {
        int c = g_cnt[i];
        g_rowptr[i] = running;
        g_cursor[i] = running;
        g_inv[i]    = 1.0f / fmaxf((float)c, 1.0f);
        running += c;
    }
    if (t == 1023) g_rowptr[N_NODES] = sums[1023];
}

__global__ void fill_kernel(const int* __restrict__ src,
                            const int* __restrict__ dst, int n_edges) {
    int i = blockIdx.x * blockDim.x + threadIdx.x;
    if (i < n_edges) {
        int p = atomicAdd(&g_cursor[dst[i]], 1);
        g_srcsort[p] = src[i];
    }
}

// ---------------------------------------------------------------------------
// Gather-only mean aggregation. F4 = float4 per feature row (32 -> 128 feats,
// 16 -> 64 feats). 32/F4 nodes per warp; lane slice l handles float4 #l.
// Output is already scaled by inv_deg.
// ---------------------------------------------------------------------------
template<int F4>
__global__ void agg_kernel(const float4* __restrict__ h4,
                           float4* __restrict__ out4) {
    constexpr int NPW = 32 / F4;
    int gtid = blockIdx.x * blockDim.x + threadIdx.x;
    int w    = gtid >> 5;
    int lane = gtid & 31;
    int v    = w * NPW + lane / F4;
    int l    = lane % F4;
    if (v >= N_NODES) return;
    int beg = g_rowptr[v];
    int end = g_rowptr[v + 1];
    float4 acc = make_float4(0.f, 0.f, 0.f, 0.f);
    int e = beg;
#pragma unroll 1
    for (; e + 1 < end; e += 2) {
        int s0 = __ldg(&g_srcsort[e]);
        int s1 = __ldg(&g_srcsort[e + 1]);
        float4 t0 = __ldg(&h4[(size_t)s0 * F4 + l]);
        float4 t1 = __ldg(&h4[(size_t)s1 * F4 + l]);
        acc.x += t0.x + t1.x; acc.y += t0.y + t1.y;
        acc.z += t0.z + t1.z; acc.w += t0.w + t1.w;
    }
    if (e < end) {
        int s0 = __ldg(&g_srcsort[e]);
        float4 t0 = __ldg(&h4[(size_t)s0 * F4 + l]);
        acc.x += t0.x; acc.y += t0.y; acc.z += t0.z; acc.w += t0.w;
    }
    float iv = g_inv[v];
    out4[(size_t)v * F4 + l] = make_float4(acc.x * iv, acc.y * iv,
                                           acc.z * iv, acc.w * iv);
}

// ---------------------------------------------------------------------------
// K=256 fused GEMM: out[n,128] = [h | agg] (n x 256) @ [Wself; Wneigh] + b,
// optional relu. agg is pre-scaled. 256 threads, BM=64, 4x8 thread tile.
// smem: W 128KB + A 69.6KB = 200704 bytes (1 block/SM).
// ---------------------------------------------------------------------------
#define SMEM_GEMM256 200704

template<bool RELU>
__global__ void __launch_bounds__(256, 1)
gemm256(const float* h, const float* __restrict__ Wself,
        const float* __restrict__ Wneigh, const float* __restrict__ bias,
        float* out, int n) {
    constexpr int BN = 128, BM = 64, CG = 16, ASTRIDE = BM + 4;
    extern __shared__ float smem_buf[];
    float* Wsm = smem_buf;               // [256][128]
    float* Asm = smem_buf + 256 * BN;    // [256][68]

    const int tid = threadIdx.x;
    for (int i = tid; i < 128 * BN; i += 256) Wsm[i] = Wself[i];
    for (int i = tid; i < 128 * BN; i += 256) Wsm[128 * BN + i] = Wneigh[i];

    const int k = tid;                   // concat-feature column
    const float* abase = (k < 128) ? (h + k) : (g_agg + (k - 128));
    const int row0 = blockIdx.x * BM;

#pragma unroll 4
    for (int i = 0; i < BM; i++) {
        int r = row0 + i;
        Asm[k * ASTRIDE + i] = (r < n) ? __ldg(&abase[(size_t)r * 128]) : 0.0f;
    }

    const int cg = tid % CG;
    const int rg = tid / CG;
    float bv[8];
#pragma unroll
    for (int c = 0; c < 8; c++) bv[c] = bias[cg * 8 + c];

    __syncthreads();

    float acc[4][8];
#pragma unroll
    for (int r = 0; r < 4; r++)
#pragma unroll
        for (int c = 0; c < 8; c++) acc[r][c] = 0.0f;

#pragma unroll 4
    for (int kk = 0; kk < 256; kk++) {
        float4 a4 = *reinterpret_cast<const float4*>(&Asm[kk * ASTRIDE + rg * 4]);
        float4 w0 = *reinterpret_cast<const float4*>(&Wsm[kk * BN + cg * 8]);
        float4 w1 = *reinterpret_cast<const float4*>(&Wsm[kk * BN + cg * 8 + 4]);
        float av[4] = {a4.x, a4.y, a4.z, a4.w};
        float wv[8] = {w0.x, w0.y, w0.z, w0.w, w1.x, w1.y, w1.z, w1.w};
#pragma unroll
        for (int r = 0; r < 4; r++)
#pragma unroll
            for (int c = 0; c < 8; c++)
                acc[r][c] = fmaf(av[r], wv[c], acc[r][c]);
    }

#pragma unroll
    for (int r = 0; r < 4; r++) {
        int grow = row0 + rg * 4 + r;
        if (grow < n) {
            float o[8];
#pragma unroll
            for (int c = 0; c < 8; c++) {
                float v = acc[r][c] + bv[c];
                if (RELU) v = fmaxf(v, 0.0f);
                o[c] = v;
            }
            float4* po = reinterpret_cast<float4*>(&out[(size_t)grow * BN + cg * 8]);
            po[0] = make_float4(o[0], o[1], o[2], o[3]);
            po[1] = make_float4(o[4], o[5], o[6], o[7]);
        }
    }
}

// ---------------------------------------------------------------------------
// K=128 GEMM: out[n,64] = A(n x 128) @ W(128 x 64) [+ bias] [+ addend].
// 256 threads, BM=128, 4x8 thread tile. smem 100352B -> 2 blocks/SM.
// ---------------------------------------------------------------------------
#define SMEM_GEMM128 100352

template<bool BIAS, bool ADDC>
__global__ void __launch_bounds__(256, 2)
gemm128(const float* __restrict__ A, const float* __restrict__ W,
        const float* __restrict__ bias, const float* __restrict__ addend,
        float* __restrict__ out, int n) {
    constexpr int BN = 64, BM = 128, CG = 8, ASTRIDE = BM + 4;
    extern __shared__ float smem_buf[];
    float* Wsm = smem_buf;               // [128][64]
    float* Asm = smem_buf + 128 * BN;    // [128][132]

    const int tid = threadIdx.x;
    for (int i = tid; i < 128 * BN; i += 256) Wsm[i] = W[i];

    const int k    = tid & 127;
    const int half = tid >> 7;
    const int row0 = blockIdx.x * BM;

#pragma unroll 4
    for (int i = half * 64; i < half * 64 + 64; i++) {
        int r = row0 + i;
        Asm[k * ASTRIDE + i] = (r < n) ? __ldg(&A[(size_t)r * 128 + k]) : 0.0f;
    }

    const int cg = tid % CG;
    const int rg = tid / CG;
    float bv[8];
#pragma unroll
    for (int c = 0; c < 8; c++) bv[c] = BIAS ? bias[cg * 8 + c] : 0.0f;

    __syncthreads();

    float acc[4][8];
#pragma unroll
    for (int r = 0; r < 4; r++)
#pragma unroll
        for (int c = 0; c < 8; c++) acc[r][c] = 0.0f;

#pragma unroll 4
    for (int kk = 0; kk < 128; kk++) {
        float4 a4 = *reinterpret_cast<const float4*>(&Asm[kk * ASTRIDE + rg * 4]);
        float4 w0 = *reinterpret_cast<const float4*>(&Wsm[kk * BN + cg * 8]);
        float4 w1 = *reinterpret_cast<const float4*>(&Wsm[kk * BN + cg * 8 + 4]);
        float av[4] = {a4.x, a4.y, a4.z, a4.w};
        float wv[8] = {w0.x, w0.y, w0.z, w0.w, w1.x, w1.y, w1.z, w1.w};
#pragma unroll
        for (int r = 0; r < 4; r++)
#pragma unroll
            for (int c = 0; c < 8; c++)
                acc[r][c] = fmaf(av[r], wv[c], acc[r][c]);
    }

#pragma unroll
    for (int r = 0; r < 4; r++) {
        int grow = row0 + rg * 4 + r;
        if (grow < n) {
            float o[8];
            if (ADDC) {
                const float4* pa =
                    reinterpret_cast<const float4*>(&addend[(size_t)grow * BN + cg * 8]);
                float4 c0 = __ldg(&pa[0]);
                float4 c1 = __ldg(&pa[1]);
                o[0] = c0.x; o[1] = c0.y; o[2] = c0.z; o[3] = c0.w;
                o[4] = c1.x; o[5] = c1.y; o[6] = c1.z; o[7] = c1.w;
            } else {
#pragma unroll
                for (int c = 0; c < 8; c++) o[c] = 0.0f;
            }
#pragma unroll
            for (int c = 0; c < 8; c++) o[c] += acc[r][c] + bv[c];
            float4* po = reinterpret_cast<float4*>(&out[(size_t)grow * BN + cg * 8]);
            po[0] = make_float4(o[0], o[1], o[2], o[3]);
            po[1] = make_float4(o[4], o[5], o[6], o[7]);
        }
    }
}

// ---------------------------------------------------------------------------
// In-place log_softmax over 64 classes. One warp per row, 2 cols/lane.
// ---------------------------------------------------------------------------
__global__ void logsoftmax_kernel(float* __restrict__ out, int n) {
    int gtid = blockIdx.x * blockDim.x + threadIdx.x;
    int row  = gtid >> 5;
    int lane = gtid & 31;
    if (row >= n) return;
    float* p = out + (size_t)row * 64;
    float a = p[lane];
    float b = p[lane + 32];
    float m = fmaxf(a, b);
#pragma unroll
    for (int o = 16; o > 0; o >>= 1)
        m = fmaxf(m, __shfl_xor_sync(0xFFFFFFFFu, m, o));
    float s = expf(a - m) + expf(b - m);
#pragma unroll
    for (int o = 16; o > 0; o >>= 1)
        s += __shfl_xor_sync(0xFFFFFFFFu, s, o);
    float l = m + logf(s);
    p[lane]      = a - l;
    p[lane + 32] = b - l;
}

// ---------------------------------------------------------------------------
extern "C" void kernel_launch(void* const* d_in, const int* in_sizes, int n_in,
                              void* d_out, int out_size) {
    const float* x   = (const float*)d_in[0];
    const int*   src = (const int*)  d_in[1];
    const int*   dst = (const int*)  d_in[2];
    const float* Ws0 = (const float*)d_in[3];
    const float* Wn0 = (const float*)d_in[4];
    const float* b0  = (const float*)d_in[5];
    const float* Ws1 = (const float*)d_in[6];
    const float* Wn1 = (const float*)d_in[7];
    const float* b1  = (const float*)d_in[8];
    const float* Ws2 = (const float*)d_in[9];
    const float* Wn2 = (const float*)d_in[10];
    const float* b2  = (const float*)d_in[11];
    float* out = (float*)d_out;

    const int n = N_NODES;
    const int E = in_sizes[1];

    float *h1p, *h2p, *aggp;
    int   *cntp;
    cudaGetSymbolAddress((void**)&h1p,  g_h1);
    cudaGetSymbolAddress((void**)&h2p,  g_h2);
    cudaGetSymbolAddress((void**)&aggp, g_agg);
    cudaGetSymbolAddress((void**)&cntp, g_cnt);

    cudaFuncSetAttribute(gemm256<true>,
                         cudaFuncAttributeMaxDynamicSharedMemorySize, SMEM_GEMM256);
    cudaFuncSetAttribute(gemm128<false, false>,
                         cudaFuncAttributeMaxDynamicSharedMemorySize, SMEM_GEMM128);
    cudaFuncSetAttribute(gemm128<true, true>,
                         cudaFuncAttributeMaxDynamicSharedMemorySize, SMEM_GEMM128);

    const int eb = (E + 255) / 256;
    const int t256 = (n + 63) / 64;     // gemm256 tiles (BM=64)
    const int t128 = (n + 127) / 128;   // gemm128 tiles (BM=128)

    // ---- CSR build (counting sort by dst) ----
    zero_int_kernel<<<(n + 1 + 255) / 256, 256>>>(cntp, n + 1);         // 0
    count_kernel<<<eb, 256>>>(dst, E);                                   // 1
    scan_kernel<<<1, 1024>>>();                                          // 2
    fill_kernel<<<eb, 256>>>(src, dst, E);                               // 3

    // ---- layer 0: x -> h1 (relu) ----
    agg_kernel<32><<<(n * 32 + 255) / 256, 256>>>(                       // 4
        (const float4*)x, (float4*)aggp);
    gemm256<true><<<t256, 256, SMEM_GEMM256>>>(x, Ws0, Wn0, b0, h1p, n); // 5

    // ---- layer 1: h1 -> h2 (relu) ----
    agg_kernel<32><<<(n * 32 + 255) / 256, 256>>>(                       // 6
        (const float4*)h1p, (float4*)aggp);
    gemm256<true><<<t256, 256, SMEM_GEMM256>>>(h1p, Ws1, Wn1, b1, h2p, n); // 7

    // ---- layer 2: project-then-aggregate ----
    // P = h2 @ Wn2  (reuse g_h1 as [n,64] buffer)
    gemm128<false, false><<<t128, 256, SMEM_GEMM128>>>(                  // 8
        h2p, Wn2, nullptr, nullptr, h1p, n);
    // agg64 = mean-aggregate P -> g_agg (64 feats, inv applied)
    agg_kernel<16><<<(n * 16 + 255) / 256, 256>>>(                       // 9
        (const float4*)h1p, (float4*)aggp);
    // out = h2 @ Ws2 + b2 + agg64
    gemm128<true, true><<<t128, 256, SMEM_GEMM128>>>(                    // 10
        h2p, Ws2, b2, aggp, out, n);

    logsoftmax_kernel<<<(n * 32 + 255) / 256, 256>>>(out, n);            // 11
}